// round 6
// baseline (speedup 1.0000x reference)
#include <cuda_runtime.h>

// ---------------------------------------------------------------------------
// SpatioTemporalGNNLayer: out = relu(conv3x3(x,Ww)+Wb + conv3x3(agg,Bw)+Bb)
// agg[dst] = mean over incoming edges of x[src].
//
// CSR build, then one fused per-node kernel. Conv uses fma.rn.f32x2 with
// dual-alignment smem rows. Warp = 8 rows x 4 cogs so every image load is a
// single conflict-free 128B wavefront; thread = 16 px x 2 output channels.
// ---------------------------------------------------------------------------

#define NNODES 4096
#define NODE_ELEMS 4096          // 16*16*16
#define RS 36                    // row: [0,x0..x15,0,pad,pad | x0..x15] (144B)
#define CHS (18*RS)              // 18 rows (zero row above+below) = 648 floats
#define IMG_FLOATS (32*CHS)      // 20736 (x image 16ch + agg image 16ch)
#define WP_FLOAT2 2304           // duplicated weight pairs for one conv
#define NMASK (NNODES-1)

__device__ int g_deg[NNODES];
__device__ int g_cur[NNODES];
__device__ int g_off[NNODES + 1];
__device__ int g_srcs[16384 * 4];
__device__ int g_is64;

// ---------------------------------------------------------------------------
__global__ void prep_kernel(const int* __restrict__ ei32, int E) {
    int i = blockIdx.x * blockDim.x + threadIdx.x;
    if (i < NNODES) { g_deg[i] = 0; g_cur[i] = 0; }
    if (blockIdx.x == 0 && threadIdx.x < 32) {
        int n = (E < 32) ? E : 32;
        int odd = (threadIdx.x < n) ? ei32[2 * threadIdx.x + 1] : 0;
        unsigned nz = __ballot_sync(0xffffffffu, odd != 0);
        if (threadIdx.x == 0) g_is64 = (nz == 0);
    }
}

__device__ __forceinline__ int load_idx(const int* ei32, int pos) {
    return g_is64 ? (ei32[2 * pos] & NMASK) : (ei32[pos] & NMASK);
}

__global__ void count_kernel(const int* __restrict__ ei32, int E) {
    int e = blockIdx.x * blockDim.x + threadIdx.x;
    if (e < E) atomicAdd(&g_deg[load_idx(ei32, E + e)], 1);
}

__global__ void scanfill_kernel(const int* __restrict__ ei32, int E) {
    __shared__ int wsum[32];
    int t = threadIdx.x;
    int lane = t & 31, wid = t >> 5;
    int4 v = ((const int4*)g_deg)[t];
    int sum = v.x + v.y + v.z + v.w;
    int s = sum;
#pragma unroll
    for (int d = 1; d < 32; d <<= 1) {
        int n = __shfl_up_sync(0xffffffffu, s, d);
        if (lane >= d) s += n;
    }
    if (lane == 31) wsum[wid] = s;
    __syncthreads();
    if (wid == 0) {
        int ws = wsum[lane];
#pragma unroll
        for (int d = 1; d < 32; d <<= 1) {
            int n = __shfl_up_sync(0xffffffffu, ws, d);
            if (lane >= d) ws += n;
        }
        wsum[lane] = ws;
    }
    __syncthreads();
    int excl = ((wid > 0) ? wsum[wid - 1] : 0) + s - sum;
    g_off[4 * t + 0] = excl;
    g_off[4 * t + 1] = excl + v.x;
    g_off[4 * t + 2] = excl + v.x + v.y;
    g_off[4 * t + 3] = excl + v.x + v.y + v.z;
    if (t == 1023) g_off[NNODES] = wsum[31];
    __syncthreads();
    for (int e = t; e < E; e += 1024) {
        int sc = load_idx(ei32, e);
        int d  = load_idx(ei32, E + e);
        int pos = g_off[d] + atomicAdd(&g_cur[d], 1);
        g_srcs[pos] = sc;
    }
}

// ---------------------------------------------------------------------------
__device__ __forceinline__ float2 ffma2(float2 a, float2 b, float2 c) {
    float2 d;
    asm("{\n\t"
        ".reg .b64 ta, tb, tc;\n\t"
        "mov.b64 ta, {%2, %3};\n\t"
        "mov.b64 tb, {%4, %5};\n\t"
        "mov.b64 tc, {%6, %7};\n\t"
        "fma.rn.f32x2 tc, ta, tb, tc;\n\t"
        "mov.b64 {%0, %1}, tc;\n\t"
        "}"
        : "=f"(d.x), "=f"(d.y)
        : "f"(a.x), "f"(a.y), "f"(b.x), "f"(b.y), "f"(c.x), "f"(c.y));
    return d;
}

// One conv over a 16-channel image: this thread's 2 output channels x 16 px
// (8 pixel pairs) of one output row.
// Row layout (36 floats): [0, x0..x15, 0, pad, pad, x0..x15]
//   P[k] = {x_{2k-1}, x_{2k}} at words 2k (taps -1/+1), k=0..8
//   S[k] = {x_{2k},  x_{2k+1}} at words 20+2k (tap 0),  k=0..7
// Weight pairs wp[(ci*9 + 3r + t)*16 + co] = (w,w).
__device__ __forceinline__ void conv_phase(const float* __restrict__ img,
                                           const float2* __restrict__ wp,
                                           int row, int co0,
                                           float2 acc0[8], float2 acc1[8]) {
#pragma unroll 2
    for (int ci = 0; ci < 16; ci++) {
        const float* ch = img + ci * CHS;
#pragma unroll
        for (int r = 0; r < 3; r++) {
            const float* rp = ch + (row + r) * RS;
            float4 p0 = *(const float4*)(rp);
            float4 p1 = *(const float4*)(rp + 4);
            float4 p2 = *(const float4*)(rp + 8);
            float4 p3 = *(const float4*)(rp + 12);
            float2 p4 = *(const float2*)(rp + 16);
            float4 s0 = *(const float4*)(rp + 20);
            float4 s1 = *(const float4*)(rp + 24);
            float4 s2 = *(const float4*)(rp + 28);
            float4 s3 = *(const float4*)(rp + 32);
            float2 P[9] = { make_float2(p0.x, p0.y), make_float2(p0.z, p0.w),
                            make_float2(p1.x, p1.y), make_float2(p1.z, p1.w),
                            make_float2(p2.x, p2.y), make_float2(p2.z, p2.w),
                            make_float2(p3.x, p3.y), make_float2(p3.z, p3.w),
                            p4 };
            float2 S[8] = { make_float2(s0.x, s0.y), make_float2(s0.z, s0.w),
                            make_float2(s1.x, s1.y), make_float2(s1.z, s1.w),
                            make_float2(s2.x, s2.y), make_float2(s2.z, s2.w),
                            make_float2(s3.x, s3.y), make_float2(s3.z, s3.w) };
            const float2* wrow = wp + (ci * 9 + 3 * r) * 16 + co0;
#pragma unroll
            for (int t = 0; t < 3; t++) {
                float4 wv = *(const float4*)(wrow + t * 16);
                float2 w0 = make_float2(wv.x, wv.y);
                float2 w1 = make_float2(wv.z, wv.w);
#pragma unroll
                for (int j = 0; j < 8; j++) {
                    float2 op = (t == 0) ? P[j] : (t == 1) ? S[j] : P[j + 1];
                    acc0[j] = ffma2(w0, op, acc0[j]);
                    acc1[j] = ffma2(w1, op, acc1[j]);
                }
            }
        }
    }
}

__global__ __launch_bounds__(128, 2) void gnn_main_kernel(
    const float* __restrict__ x,
    const float* __restrict__ Ww, const float* __restrict__ Wbias,
    const float* __restrict__ Bw, const float* __restrict__ Bbias,
    float* __restrict__ out) {
    extern __shared__ float sm[];
    float*  sImg = sm;                          // 20736 floats
    float2* sWp  = (float2*)(sm + IMG_FLOATS);  // 2304 float2 (one conv)

    int tid  = threadIdx.x;
    int node = blockIdx.x;

    // zero image buffers (pads stay 0)
    float4* z4 = (float4*)sImg;
    for (int i = tid; i < IMG_FLOATS / 4; i += 128)
        z4[i] = make_float4(0.f, 0.f, 0.f, 0.f);
    // stage phase-A (Ww) duplicated weight pairs: wp[q*16+co] = (w,w)
    for (int i = tid; i < WP_FLOAT2; i += 128) {
        int co = i & 15, q = i >> 4;
        float v = Ww[co * 144 + q];
        sWp[i] = make_float2(v, v);
    }

    // gather-mean over incoming edges: 8 float4 per thread (regs)
    const float4* xp = (const float4*)(x + (size_t)node * NODE_ELEMS);
    float4 a[8];
#pragma unroll
    for (int k = 0; k < 8; k++) a[k] = make_float4(0.f, 0.f, 0.f, 0.f);
    int beg = g_off[node], end = g_off[node + 1];
    for (int e = beg; e < end; e++) {
        int sc = g_srcs[e] & NMASK;
        const float4* sp = (const float4*)(x + (size_t)sc * NODE_ELEMS);
#pragma unroll
        for (int k = 0; k < 8; k++) {
            float4 v = __ldg(&sp[tid + 128 * k]);
            a[k].x += v.x; a[k].y += v.y; a[k].z += v.z; a[k].w += v.w;
        }
    }
    float inv = 1.0f / (float)max(end - beg, 1);

    __syncthreads();   // zeros + Ww pairs in place

    // scatter x + agg into dual-alignment rows
#pragma unroll
    for (int k = 0; k < 8; k++) {
        int i4  = tid + 128 * k;
        int ci  = i4 >> 6;
        int rem = i4 & 63;
        int y   = rem >> 2;
        int m   = (rem & 3) * 4;
        float* bx = sImg + ci * CHS + (y + 1) * RS;
        float* ba = sImg + (16 + ci) * CHS + (y + 1) * RS;
        float4 xv = xp[i4];
        bx[1 + m] = xv.x; bx[2 + m] = xv.y; bx[3 + m] = xv.z; bx[4 + m] = xv.w;
        *(float4*)(bx + 20 + m) = xv;
        float4 av = make_float4(a[k].x * inv, a[k].y * inv, a[k].z * inv, a[k].w * inv);
        ba[1 + m] = av.x; ba[2 + m] = av.y; ba[3 + m] = av.z; ba[4 + m] = av.w;
        *(float4*)(ba + 20 + m) = av;
    }
    __syncthreads();

    // thread map: warp = 8 rows x 4 cogs (image loads: 1 wavefront each)
    int row = (tid & 7) | ((tid >> 6) << 3);
    int cog = (tid >> 3) & 7;
    int co0 = 2 * cog;

    float2 acc0[8], acc1[8];
    float bz0 = __ldg(&Wbias[co0]) + __ldg(&Bbias[co0]);
    float bz1 = __ldg(&Wbias[co0 + 1]) + __ldg(&Bbias[co0 + 1]);
#pragma unroll
    for (int j = 0; j < 8; j++) {
        acc0[j] = make_float2(bz0, bz0);
        acc1[j] = make_float2(bz1, bz1);
    }

    // phase A: conv(x, Ww)
    conv_phase(sImg, sWp, row, co0, acc0, acc1);

    __syncthreads();   // done reading Ww pairs
    for (int i = tid; i < WP_FLOAT2; i += 128) {
        int co = i & 15, q = i >> 4;
        float v = Bw[co * 144 + q];
        sWp[i] = make_float2(v, v);
    }
    __syncthreads();

    // phase B: conv(agg, Bw)
    conv_phase(sImg + 16 * CHS, sWp, row, co0, acc0, acc1);

    // relu + store: 16 px for each of 2 cos
    float* o0 = out + (size_t)node * NODE_ELEMS + co0 * 256 + row * 16;
    float* o1 = o0 + 256;
#pragma unroll
    for (int q = 0; q < 4; q++) {
        ((float4*)o0)[q] = make_float4(
            fmaxf(acc0[2 * q].x, 0.f), fmaxf(acc0[2 * q].y, 0.f),
            fmaxf(acc0[2 * q + 1].x, 0.f), fmaxf(acc0[2 * q + 1].y, 0.f));
        ((float4*)o1)[q] = make_float4(
            fmaxf(acc1[2 * q].x, 0.f), fmaxf(acc1[2 * q].y, 0.f),
            fmaxf(acc1[2 * q + 1].x, 0.f), fmaxf(acc1[2 * q + 1].y, 0.f));
    }
}

// ---------------------------------------------------------------------------
extern "C" void kernel_launch(void* const* d_in, const int* in_sizes, int n_in,
                              void* d_out, int out_size) {
    const float* x   = (const float*)d_in[0];
    const int*   ei  = (const int*)d_in[1];   // int32 view; prep detects dtype
    const float* Ww  = (const float*)d_in[2];
    const float* Wb  = (const float*)d_in[3];
    const float* Bw  = (const float*)d_in[4];
    const float* Bb  = (const float*)d_in[5];
    float*       out = (float*)d_out;

    int E = in_sizes[1] / 2;
    int N = in_sizes[0] / NODE_ELEMS;

    prep_kernel<<<(NNODES + 255) / 256, 256>>>(ei, E);
    count_kernel<<<(E + 255) / 256, 256>>>(ei, E);
    scanfill_kernel<<<1, 1024>>>(ei, E);

    int smem_bytes = (IMG_FLOATS + 2 * WP_FLOAT2) * (int)sizeof(float);  // 101376
    cudaFuncSetAttribute(gnn_main_kernel,
                         cudaFuncAttributeMaxDynamicSharedMemorySize, smem_bytes);
    gnn_main_kernel<<<N, 128, smem_bytes>>>(x, Ww, Wb, Bw, Bb, out);
}